// round 17
// baseline (speedup 1.0000x reference)
#include <cuda_runtime.h>
#include <cuda_fp16.h>
#include <math.h>

// ---------------------------------------------------------------------------
// Mamba block forward. fp16 mma.sync GEMMs (128x64 tile, cp.async 3-stage,
// occ=4); fp16 streams, __half2-vectorized; chunked selective scan
// (geometric-dA, CHUNK=32), gate computed in-scan from xz (no gateh buffer).
//   B=2, L=2048, d_model=1024, d_inner=2048, d_state=16, d_conv=4, dt_rank=64
// tcgen05 unavailable: harness PTX target is compute_103 (no 'a' suffix).
// ---------------------------------------------------------------------------

#define L_SEQ   2048
#define NB      2
#define DMODEL  1024
#define DINNER  2048
#define DSTATE  16
#define NROWS   (NB * L_SEQ)     // 4096
#define XPROJ_N 96
#define KSPLIT  8
#define CHUNK   32
#define NCHUNK  (L_SEQ / CHUNK)  // 64

// fp32 scratch
__device__ float g_xpart [(size_t)KSPLIT * NROWS * XPROJ_N];
__device__ float g_xdbl  [(size_t)NROWS * XPROJ_N];
__device__ float g_hfin  [(size_t)NB * NCHUNK * DSTATE * DINNER];
__device__ float g_hini  [(size_t)NB * NCHUNK * DSTATE * DINNER];
__device__ float g_sumd  [(size_t)NB * NCHUNK * DINNER];
// fp16 operands / activations
__device__ __half g_xzh   [(size_t)NROWS * 2 * DINNER];
__device__ __half g_xh    [(size_t)NROWS * DMODEL];
__device__ __half g_whin  [(size_t)2 * DINNER * DMODEL];
__device__ __half g_whxp  [(size_t)XPROJ_N * DINNER];
__device__ __half g_whdt  [(size_t)DINNER * 64];
__device__ __half g_whout [(size_t)DMODEL * DINNER];
__device__ __half g_uch   [(size_t)NROWS * DINNER];
__device__ __half g_xdblh [(size_t)NROWS * XPROJ_N];
__device__ __half g_deltah[(size_t)NROWS * DINNER];
__device__ __half g_yh    [(size_t)NROWS * DINNER];

__device__ __forceinline__ float softplusf(float x) {
    return x > 20.f ? x : log1pf(__expf(x));
}
__device__ __forceinline__ unsigned smem_u32(const void* p) {
    return (unsigned)__cvta_generic_to_shared(p);
}
__device__ __forceinline__ void cp_async16(unsigned saddr, const void* gptr, int sz) {
    asm volatile("cp.async.cg.shared.global [%0], [%1], 16, %2;"
                 :: "r"(saddr), "l"(gptr), "r"(sz));
}
__device__ __forceinline__ void cp_commit() {
    asm volatile("cp.async.commit_group;" ::: "memory");
}
template<int N>
__device__ __forceinline__ void cp_wait() {
    asm volatile("cp.async.wait_group %0;" :: "n"(N) : "memory");
}

__device__ __forceinline__ bool load_na(const float* __restrict__ A_log,
                                        int d, float* na)
{
    bool geo = true;
#pragma unroll
    for (int s = 0; s < DSTATE; ++s) {
        na[s] = -__expf(A_log[(size_t)d * DSTATE + s]);
        geo = geo && (fabsf(na[s] - (float)(s + 1) * na[0])
                      <= 1e-5f * fabsf(na[s]));
    }
    return geo;
}

// ---------------------------------------------------------------------------
__global__ __launch_bounds__(256)
void f2h_multi(const float* __restrict__ s0, __half* d0, int n0,
               const float* __restrict__ s1, __half* d1, int n1,
               const float* __restrict__ s2, __half* d2, int n2,
               const float* __restrict__ s3, __half* d3, int n3,
               const float* __restrict__ s4, __half* d4, int n4)
{
    const float* s; __half* d; int n;
    switch (blockIdx.y) {
        case 0: s = s0; d = d0; n = n0; break;
        case 1: s = s1; d = d1; n = n1; break;
        case 2: s = s2; d = d2; n = n2; break;
        case 3: s = s3; d = d3; n = n3; break;
        default: s = s4; d = d4; n = n4; break;
    }
    int nq = n >> 2;
    for (int i = blockIdx.x * blockDim.x + threadIdx.x; i < nq;
         i += gridDim.x * blockDim.x) {
        float4 v = *reinterpret_cast<const float4*>(s + (size_t)i * 4);
        __half2 h0 = __floats2half2_rn(v.x, v.y);
        __half2 h1 = __floats2half2_rn(v.z, v.w);
        *reinterpret_cast<uint2*>(d + (size_t)i * 4) =
            make_uint2(*(unsigned*)&h0, *(unsigned*)&h1);
    }
}

// ---------------------------------------------------------------------------
// fp16 GEMM, 128x64 CTA tile, m16n8k16, cp.async 3-stage ring, occ=4.
// EPI=0: fp32 C (split-K slice). EPI=1: fp16 softplus(acc+bias). EPI=2: fp16 C.
// ---------------------------------------------------------------------------
#define BK      32
#define BSTH    40
#define A_STG   (128 * BSTH)
#define B_STG   (64 * BSTH)
#define STG_H   (A_STG + B_STG)
#define NSTAGE  3
#define MMA_SMEM_BYTES (NSTAGE * STG_H * 2)   // 46080

template<int EPI>
__global__ __launch_bounds__(256, 4)
void mma_tn(const __half* __restrict__ A, const __half* __restrict__ B,
            void* __restrict__ Cv, int M, int N, int K,
            int lda, int ldb, int ldc,
            const float* __restrict__ bias, int kPerSplit)
{
    extern __shared__ __align__(16) __half sh[];

    const int tid  = threadIdx.x;
    const int lane = tid & 31;
    const int wid  = tid >> 5;
    const int wm0  = (wid >> 1) << 5;
    const int wn0  = (wid & 1) << 5;

    const int bm = blockIdx.y << 7;
    const int bn = blockIdx.x << 6;
    const int kbeg = blockIdx.z * kPerSplit;

    float acc[2][4][4];
#pragma unroll
    for (int mt = 0; mt < 2; ++mt)
#pragma unroll
        for (int nt = 0; nt < 4; ++nt)
#pragma unroll
            for (int r = 0; r < 4; ++r) acc[mt][nt][r] = 0.f;

    int a_off[2], b_off[2];
#pragma unroll
    for (int mt = 0; mt < 2; ++mt) {
        int row = wm0 + mt * 16 + ((lane >> 3) & 1) * 8 + (lane & 7);
        int col = (lane >> 4) * 8;
        a_off[mt] = row * BSTH + col;
    }
#pragma unroll
    for (int bt = 0; bt < 2; ++bt) {
        int row = wn0 + bt * 16 + ((lane >> 3) & 1) * 8 + (lane & 7);
        int col = (lane >> 4) * 8;
        b_off[bt] = A_STG + row * BSTH + col;
    }
    const unsigned sh_base = smem_u32(sh);

    const int lrow = tid >> 2;
    const int lc8  = (tid & 3) << 3;

    const __half* gA0 = A + (size_t)(bm + lrow) * lda + kbeg + lc8;
    const __half* gA1 = gA0 + (size_t)64 * lda;
    int rb  = (bn + lrow < N) ? lrow : 0;
    int bsz = (bn + lrow < N) ? 16 : 0;
    const __half* gB0 = B + (size_t)(bn + rb) * ldb + kbeg + lc8;

    const int nk = kPerSplit >> 5;
    const unsigned s_arow0 = (unsigned)((lrow * BSTH + lc8) << 1);
    const unsigned s_arow1 = (unsigned)(((lrow + 64) * BSTH + lc8) << 1);
    const unsigned s_brow  = (unsigned)((A_STG + lrow * BSTH + lc8) << 1);

    auto issue = [&](int t) {
        if (t < nk) {
            unsigned sb = sh_base + (unsigned)(((t % NSTAGE) * STG_H) << 1);
            int koff = t * BK;
            cp_async16(sb + s_arow0, gA0 + koff, 16);
            cp_async16(sb + s_arow1, gA1 + koff, 16);
            cp_async16(sb + s_brow,  gB0 + koff, bsz);
        }
        cp_commit();
    };

    issue(0);
    issue(1);

    for (int t = 0; t < nk; ++t) {
        cp_wait<1>();
        __syncthreads();
        issue(t + 2);

        const unsigned st_base = sh_base + (unsigned)(((t % NSTAGE) * STG_H) << 1);

#pragma unroll
        for (int kk = 0; kk < BK; kk += 16) {
            unsigned a[2][4], b[2][4];
#pragma unroll
            for (int mt = 0; mt < 2; ++mt) {
                unsigned addr = st_base + (unsigned)((a_off[mt] + kk) << 1);
                asm volatile(
                    "ldmatrix.sync.aligned.m8n8.x4.shared.b16 {%0,%1,%2,%3}, [%4];"
                    : "=r"(a[mt][0]), "=r"(a[mt][1]), "=r"(a[mt][2]), "=r"(a[mt][3])
                    : "r"(addr));
            }
#pragma unroll
            for (int bt = 0; bt < 2; ++bt) {
                unsigned addr = st_base + (unsigned)((b_off[bt] + kk) << 1);
                asm volatile(
                    "ldmatrix.sync.aligned.m8n8.x4.shared.b16 {%0,%1,%2,%3}, [%4];"
                    : "=r"(b[bt][0]), "=r"(b[bt][1]), "=r"(b[bt][2]), "=r"(b[bt][3])
                    : "r"(addr));
            }
#pragma unroll
            for (int mt = 0; mt < 2; ++mt)
#pragma unroll
                for (int nt = 0; nt < 4; ++nt) {
                    unsigned b0 = b[nt >> 1][(nt & 1)];
                    unsigned b1 = b[nt >> 1][2 + (nt & 1)];
                    asm volatile(
                        "mma.sync.aligned.m16n8k16.row.col.f32.f16.f16.f32 "
                        "{%0,%1,%2,%3}, {%4,%5,%6,%7}, {%8,%9}, {%0,%1,%2,%3};"
                        : "+f"(acc[mt][nt][0]), "+f"(acc[mt][nt][1]),
                          "+f"(acc[mt][nt][2]), "+f"(acc[mt][nt][3])
                        : "r"(a[mt][0]), "r"(a[mt][1]), "r"(a[mt][2]), "r"(a[mt][3]),
                          "r"(b0), "r"(b1));
                }
        }
    }

    const int gid = lane >> 2;
    const int tig = lane & 3;
#pragma unroll
    for (int mt = 0; mt < 2; ++mt)
#pragma unroll
        for (int nt = 0; nt < 4; ++nt) {
            int m = bm + wm0 + mt * 16 + gid;
            int n = bn + wn0 + nt * 8 + tig * 2;
            if (n < N) {
                float v0 = acc[mt][nt][0], v1 = acc[mt][nt][1];
                float v2 = acc[mt][nt][2], v3 = acc[mt][nt][3];
                if (EPI == 1) {
                    float b0v = bias[n], b1v = bias[n + 1];
                    v0 = softplusf(v0 + b0v); v1 = softplusf(v1 + b1v);
                    v2 = softplusf(v2 + b0v); v3 = softplusf(v3 + b1v);
                    __half* C = (__half*)Cv;
                    *reinterpret_cast<__half2*>(C + (size_t)m * ldc + n) =
                        __floats2half2_rn(v0, v1);
                    *reinterpret_cast<__half2*>(C + (size_t)(m + 8) * ldc + n) =
                        __floats2half2_rn(v2, v3);
                } else if (EPI == 2) {
                    __half* C = (__half*)Cv;
                    *reinterpret_cast<__half2*>(C + (size_t)m * ldc + n) =
                        __floats2half2_rn(v0, v1);
                    *reinterpret_cast<__half2*>(C + (size_t)(m + 8) * ldc + n) =
                        __floats2half2_rn(v2, v3);
                } else {
                    float* C = (float*)Cv + (size_t)blockIdx.z * (size_t)M * (size_t)ldc;
                    *reinterpret_cast<float2*>(C + (size_t)m * ldc + n) =
                        make_float2(v0, v1);
                    *reinterpret_cast<float2*>(C + (size_t)(m + 8) * ldc + n) =
                        make_float2(v2, v3);
                }
            }
        }
}

// ---------------------------------------------------------------------------
// conv + silu, __half2-vectorized: each thread handles 2 channels.
// ---------------------------------------------------------------------------
__global__ __launch_bounds__(256)
void conv_silu_k(const __half* __restrict__ xz, const float* __restrict__ w,
                 const float* __restrict__ cb, __half* __restrict__ uch)
{
    int idx = blockIdx.x * blockDim.x + threadIdx.x;
    if (idx >= NROWS * (DINNER / 2)) return;
    int dp  = idx & (DINNER / 2 - 1);
    int d2  = dp << 1;
    int row = idx >> 10;
    int l   = row & (L_SEQ - 1);
    int b   = row >> 11;

    const float4 w0 = *reinterpret_cast<const float4*>(w + (size_t)d2 * 4);
    const float4 w1 = *reinterpret_cast<const float4*>(w + (size_t)(d2 + 1) * 4);
    const float2 cbv = *reinterpret_cast<const float2*>(cb + d2);

    const __half* up = xz + (size_t)b * L_SEQ * (2 * DINNER) + d2;
    const size_t S = 2 * DINNER;

    float2 v;
    float a0 = cbv.x, a1 = cbv.y;
    v = __half22float2(*reinterpret_cast<const __half2*>(up + (size_t)l * S));
    a0 = fmaf(w0.w, v.x, a0); a1 = fmaf(w1.w, v.y, a1);
    if (l >= 1) {
        v = __half22float2(*reinterpret_cast<const __half2*>(up + (size_t)(l - 1) * S));
        a0 = fmaf(w0.z, v.x, a0); a1 = fmaf(w1.z, v.y, a1);
    }
    if (l >= 2) {
        v = __half22float2(*reinterpret_cast<const __half2*>(up + (size_t)(l - 2) * S));
        a0 = fmaf(w0.y, v.x, a0); a1 = fmaf(w1.y, v.y, a1);
    }
    if (l >= 3) {
        v = __half22float2(*reinterpret_cast<const __half2*>(up + (size_t)(l - 3) * S));
        a0 = fmaf(w0.x, v.x, a0); a1 = fmaf(w1.x, v.y, a1);
    }

    *reinterpret_cast<__half2*>(uch + (size_t)row * DINNER + d2) =
        __floats2half2_rn(a0 / (1.f + __expf(-a0)), a1 / (1.f + __expf(-a1)));
}

__global__ void reduce_split(const float* __restrict__ part,
                             float* __restrict__ out,
                             __half* __restrict__ outh, int n)
{
    int i = blockIdx.x * blockDim.x + threadIdx.x;
    if (i < n) {
        float s = 0.f;
#pragma unroll
        for (int z = 0; z < KSPLIT; ++z) s += part[(size_t)z * n + i];
        out[i]  = s;
        outh[i] = __float2half_rn(s);
    }
}

// ---------------------------------------------------------------------------
// Chunked selective scan, CHUNK=32 (64 chunks), 2 channels/thread, half2 IO.
// Gate silu(z) computed in p3 directly from xz (fp32 precision).
// ---------------------------------------------------------------------------
__global__ __launch_bounds__(128)
void scan_p1(const __half* __restrict__ delta, const float* __restrict__ xdbl,
             const __half* __restrict__ uc, const float* __restrict__ A_log,
             float* __restrict__ hfin, float* __restrict__ sumd)
{
    const int b = blockIdx.z;
    const int c = blockIdx.y;
    const int d0 = blockIdx.x * 256 + threadIdx.x * 2;

    float na0[DSTATE], na1[DSTATE];
    const bool geo = load_na(A_log, d0, na0) & load_na(A_log, d0 + 1, na1);
    const float n00 = na0[0], n01 = na1[0];

    float h0[DSTATE], h1[DSTATE];
#pragma unroll
    for (int s = 0; s < DSTATE; ++s) { h0[s] = 0.f; h1[s] = 0.f; }
    float sd0 = 0.f, sd1 = 0.f;

    __shared__ float bs[32][DSTATE];

    const int l0 = c * CHUNK;
    for (int t = threadIdx.x; t < 32 * DSTATE; t += 128) {
        int i = t >> 4, j = t & 15;
        bs[i][j] = xdbl[(size_t)(b * L_SEQ + l0 + i) * XPROJ_N + 64 + j];
    }
    __syncthreads();

    if (geo) {
#pragma unroll 2
        for (int i = 0; i < 32; ++i) {
            size_t row = (size_t)b * L_SEQ + l0 + i;
            float2 td = __half22float2(
                *reinterpret_cast<const __half2*>(delta + row * DINNER + d0));
            float2 ud = __half22float2(
                *reinterpret_cast<const __half2*>(uc + row * DINNER + d0));
            float tu0 = td.x * ud.x, tu1 = td.y * ud.y;
            sd0 += td.x; sd1 += td.y;
            float p0 = __expf(td.x * n00), p1 = __expf(td.y * n01);
            float q0 = p0 * p0, q1 = p1 * p1;
            float ra0 = p0, rb0 = q0, ra1 = p1, rb1 = q1;
            h0[0] = fmaf(ra0, h0[0], tu0 * bs[i][0]);
            h1[0] = fmaf(ra1, h1[0], tu1 * bs[i][0]);
            h0[1] = fmaf(rb0, h0[1], tu0 * bs[i][1]);
            h1[1] = fmaf(rb1, h1[1], tu1 * bs[i][1]);
#pragma unroll
            for (int s = 2; s < DSTATE; s += 2) {
                ra0 *= q0; ra1 *= q1;
                h0[s] = fmaf(ra0, h0[s], tu0 * bs[i][s]);
                h1[s] = fmaf(ra1, h1[s], tu1 * bs[i][s]);
                rb0 *= q0; rb1 *= q1;
                h0[s+1] = fmaf(rb0, h0[s+1], tu0 * bs[i][s+1]);
                h1[s+1] = fmaf(rb1, h1[s+1], tu1 * bs[i][s+1]);
            }
        }
    } else {
#pragma unroll 2
        for (int i = 0; i < 32; ++i) {
            size_t row = (size_t)b * L_SEQ + l0 + i;
            float2 td = __half22float2(
                *reinterpret_cast<const __half2*>(delta + row * DINNER + d0));
            float2 ud = __half22float2(
                *reinterpret_cast<const __half2*>(uc + row * DINNER + d0));
            float tu0 = td.x * ud.x, tu1 = td.y * ud.y;
            sd0 += td.x; sd1 += td.y;
#pragma unroll
            for (int s = 0; s < DSTATE; ++s) {
                h0[s] = fmaf(__expf(td.x * na0[s]), h0[s], tu0 * bs[i][s]);
                h1[s] = fmaf(__expf(td.y * na1[s]), h1[s], tu1 * bs[i][s]);
            }
        }
    }

    const size_t base = ((size_t)(b * NCHUNK + c) * DSTATE) * DINNER + d0;
#pragma unroll
    for (int s = 0; s < DSTATE; ++s)
        *reinterpret_cast<float2*>(hfin + base + (size_t)s * DINNER) =
            make_float2(h0[s], h1[s]);
    *reinterpret_cast<float2*>(sumd + (size_t)(b * NCHUNK + c) * DINNER + d0) =
        make_float2(sd0, sd1);
}

__global__ __launch_bounds__(256)
void scan_combine(const float* __restrict__ hfin, const float* __restrict__ sumd,
                  const float* __restrict__ A_log, float* __restrict__ hini)
{
    const int b = blockIdx.y;
    const int d = blockIdx.x * 256 + threadIdx.x;

    float na[DSTATE];
    load_na(A_log, d, na);

    float h[DSTATE];
#pragma unroll
    for (int s = 0; s < DSTATE; ++s) h[s] = 0.f;

    for (int c = 0; c < NCHUNK; ++c) {
        const size_t base = ((size_t)(b * NCHUNK + c) * DSTATE) * DINNER + d;
#pragma unroll
        for (int s = 0; s < DSTATE; ++s)
            hini[base + (size_t)s * DINNER] = h[s];
        float sd = sumd[(size_t)(b * NCHUNK + c) * DINNER + d];
#pragma unroll
        for (int s = 0; s < DSTATE; ++s) {
            float pA = __expf(sd * na[s]);
            h[s] = fmaf(pA, h[s], hfin[base + (size_t)s * DINNER]);
        }
    }
}

__global__ __launch_bounds__(128)
void scan_p3(const __half* __restrict__ delta, const float* __restrict__ xdbl,
             const __half* __restrict__ uc, const __half* __restrict__ xz,
             const float* __restrict__ A_log, const float* __restrict__ Dv,
             const float* __restrict__ hini, __half* __restrict__ yh)
{
    const int b = blockIdx.z;
    const int c = blockIdx.y;
    const int d0 = blockIdx.x * 256 + threadIdx.x * 2;

    float na0[DSTATE], na1[DSTATE];
    const bool geo = load_na(A_log, d0, na0) & load_na(A_log, d0 + 1, na1);
    const float n00 = na0[0], n01 = na1[0];

    float h0[DSTATE], h1[DSTATE];
    {
        const size_t base = ((size_t)(b * NCHUNK + c) * DSTATE) * DINNER + d0;
#pragma unroll
        for (int s = 0; s < DSTATE; ++s) {
            float2 hv = *reinterpret_cast<const float2*>(
                hini + base + (size_t)s * DINNER);
            h0[s] = hv.x; h1[s] = hv.y;
        }
    }

    const float2 Dd = *reinterpret_cast<const float2*>(Dv + d0);
    const __half* zp = xz + (size_t)b * L_SEQ * (2 * DINNER) + DINNER + d0;
    __shared__ float bc[32][32];

    const int l0 = c * CHUNK;
    for (int t = threadIdx.x; t < 1024; t += 128) {
        int i = t >> 5, j = t & 31;
        bc[i][j] = xdbl[(size_t)(b * L_SEQ + l0 + i) * XPROJ_N + 64 + j];
    }
    __syncthreads();

    if (geo) {
#pragma unroll 2
        for (int i = 0; i < 32; ++i) {
            size_t row = (size_t)b * L_SEQ + l0 + i;
            float2 td = __half22float2(
                *reinterpret_cast<const __half2*>(delta + row * DINNER + d0));
            float2 ud = __half22float2(
                *reinterpret_cast<const __half2*>(uc + row * DINNER + d0));
            float tu0 = td.x * ud.x, tu1 = td.y * ud.y;
            float yv0 = 0.f, yv1 = 0.f;
            float p0 = __expf(td.x * n00), p1 = __expf(td.y * n01);
            float q0 = p0 * p0, q1 = p1 * p1;
            float ra0 = p0, rb0 = q0, ra1 = p1, rb1 = q1;
            h0[0] = fmaf(ra0, h0[0], tu0 * bc[i][0]);
            h1[0] = fmaf(ra1, h1[0], tu1 * bc[i][0]);
            yv0 = fmaf(h0[0], bc[i][16], yv0);
            yv1 = fmaf(h1[0], bc[i][16], yv1);
            h0[1] = fmaf(rb0, h0[1], tu0 * bc[i][1]);
            h1[1] = fmaf(rb1, h1[1], tu1 * bc[i][1]);
            yv0 = fmaf(h0[1], bc[i][17], yv0);
            yv1 = fmaf(h1[1], bc[i][17], yv1);
#pragma unroll
            for (int s = 2; s < DSTATE; s += 2) {
                ra0 *= q0; ra1 *= q1;
                h0[s] = fmaf(ra0, h0[s], tu0 * bc[i][s]);
                h1[s] = fmaf(ra1, h1[s], tu1 * bc[i][s]);
                yv0 = fmaf(h0[s], bc[i][16 + s], yv0);
                yv1 = fmaf(h1[s], bc[i][16 + s], yv1);
                rb0 *= q0; rb1 *= q1;
                h0[s+1] = fmaf(rb0, h0[s+1], tu0 * bc[i][s+1]);
                h1[s+1] = fmaf(rb1, h1[s+1], tu1 * bc[i][s+1]);
                yv0 = fmaf(h0[s+1], bc[i][17 + s], yv0);
                yv1 = fmaf(h1[s+1], bc[i][17 + s], yv1);
            }
            float2 z = __half22float2(
                *reinterpret_cast<const __half2*>(zp + (size_t)(l0 + i) * (2 * DINNER)));
            float g0 = z.x / (1.f + __expf(-z.x));
            float g1 = z.y / (1.f + __expf(-z.y));
            *reinterpret_cast<__half2*>(yh + row * DINNER + d0) =
                __floats2half2_rn((yv0 + ud.x * Dd.x) * g0,
                                  (yv1 + ud.y * Dd.y) * g1);
        }
    } else {
#pragma unroll 2
        for (int i = 0; i < 32; ++i) {
            size_t row = (size_t)b * L_SEQ + l0 + i;
            float2 td = __half22float2(
                *reinterpret_cast<const __half2*>(delta + row * DINNER + d0));
            float2 ud = __half22float2(
                *reinterpret_cast<const __half2*>(uc + row * DINNER + d0));
            float tu0 = td.x * ud.x, tu1 = td.y * ud.y;
            float yv0 = 0.f, yv1 = 0.f;
#pragma unroll
            for (int s = 0; s < DSTATE; ++s) {
                h0[s] = fmaf(__expf(td.x * na0[s]), h0[s], tu0 * bc[i][s]);
                h1[s] = fmaf(__expf(td.y * na1[s]), h1[s], tu1 * bc[i][s]);
                yv0 = fmaf(h0[s], bc[i][16 + s], yv0);
                yv1 = fmaf(h1[s], bc[i][16 + s], yv1);
            }
            float2 z = __half22float2(
                *reinterpret_cast<const __half2*>(zp + (size_t)(l0 + i) * (2 * DINNER)));
            float g0 = z.x / (1.f + __expf(-z.x));
            float g1 = z.y / (1.f + __expf(-z.y));
            *reinterpret_cast<__half2*>(yh + row * DINNER + d0) =
                __floats2half2_rn((yv0 + ud.x * Dd.x) * g0,
                                  (yv1 + ud.y * Dd.y) * g1);
        }
    }
}

// ---------------------------------------------------------------------------
extern "C" void kernel_launch(void* const* d_in, const int* in_sizes, int n_in,
                              void* d_out, int out_size)
{
    const float* x        = (const float*)d_in[0];
    const float* W_in     = (const float*)d_in[1];
    const float* conv_w   = (const float*)d_in[2];
    const float* conv_b   = (const float*)d_in[3];
    const float* W_xproj  = (const float*)d_in[4];
    const float* W_dtproj = (const float*)d_in[5];
    const float* dt_bias  = (const float*)d_in[6];
    const float* A_log    = (const float*)d_in[7];
    const float* Dv       = (const float*)d_in[8];
    const float* W_out    = (const float*)d_in[9];
    float* out = (float*)d_out;

    float *xpart, *xdbl, *hfin, *hini, *sumd;
    __half *xzh, *xh, *whin, *whxp, *whdt, *whout, *uch, *xdblh, *deltah, *yh;
    cudaGetSymbolAddress((void**)&xpart,  g_xpart);
    cudaGetSymbolAddress((void**)&xdbl,   g_xdbl);
    cudaGetSymbolAddress((void**)&hfin,   g_hfin);
    cudaGetSymbolAddress((void**)&hini,   g_hini);
    cudaGetSymbolAddress((void**)&sumd,   g_sumd);
    cudaGetSymbolAddress((void**)&xzh,    g_xzh);
    cudaGetSymbolAddress((void**)&xh,     g_xh);
    cudaGetSymbolAddress((void**)&whin,   g_whin);
    cudaGetSymbolAddress((void**)&whxp,   g_whxp);
    cudaGetSymbolAddress((void**)&whdt,   g_whdt);
    cudaGetSymbolAddress((void**)&whout,  g_whout);
    cudaGetSymbolAddress((void**)&uch,    g_uch);
    cudaGetSymbolAddress((void**)&xdblh,  g_xdblh);
    cudaGetSymbolAddress((void**)&deltah, g_deltah);
    cudaGetSymbolAddress((void**)&yh,     g_yh);

    cudaFuncSetAttribute(mma_tn<0>,
        cudaFuncAttributeMaxDynamicSharedMemorySize, MMA_SMEM_BYTES);
    cudaFuncSetAttribute(mma_tn<1>,
        cudaFuncAttributeMaxDynamicSharedMemorySize, MMA_SMEM_BYTES);
    cudaFuncSetAttribute(mma_tn<2>,
        cudaFuncAttributeMaxDynamicSharedMemorySize, MMA_SMEM_BYTES);

    dim3 blk(256);

    // 0. convert x + all weights to fp16
    f2h_multi<<<dim3(2048, 5), blk>>>(
        x,        xh,    NROWS * DMODEL,
        W_in,     whin,  2 * DINNER * DMODEL,
        W_xproj,  whxp,  XPROJ_N * DINNER,
        W_dtproj, whdt,  DINNER * 64,
        W_out,    whout, DMODEL * DINNER);

    // 1. in_proj: xz[4096,4096] fp16 = x @ W_in^T  (K=1024)
    mma_tn<2><<<dim3(64, 32, 1), blk, MMA_SMEM_BYTES>>>(xh, whin, xzh,
        NROWS, 2 * DINNER, DMODEL, DMODEL, DMODEL, 2 * DINNER,
        nullptr, DMODEL);

    // 2. depthwise conv + silu (half2 vectorized)
    conv_silu_k<<<(NROWS * DINNER / 2) / 256, blk>>>(xzh, conv_w, conv_b, uch);

    // 3. x_proj (split-K x8)
    mma_tn<0><<<dim3(2, 32, KSPLIT), blk, MMA_SMEM_BYTES>>>(uch, whxp, xpart,
        NROWS, XPROJ_N, DINNER, DINNER, DINNER, XPROJ_N,
        nullptr, DINNER / KSPLIT);
    reduce_split<<<(NROWS * XPROJ_N + 255) / 256, blk>>>(
        xpart, xdbl, xdblh, NROWS * XPROJ_N);

    // 4. dt_proj + softplus -> fp16 delta (K=64)
    mma_tn<1><<<dim3(32, 32, 1), blk, MMA_SMEM_BYTES>>>(xdblh, whdt, deltah,
        NROWS, DINNER, 64, XPROJ_N, 64, DINNER,
        dt_bias, 64);

    // 5. chunked selective scan (CHUNK=32, 2 channels/thread)
    scan_p1<<<dim3(DINNER / 256, NCHUNK, NB), dim3(128)>>>(
        deltah, xdbl, uch, A_log, hfin, sumd);
    scan_combine<<<dim3(DINNER / 256, NB), blk>>>(hfin, sumd, A_log, hini);
    scan_p3<<<dim3(DINNER / 256, NCHUNK, NB), dim3(128)>>>(
        deltah, xdbl, uch, xzh, A_log, Dv, hini, yh);

    // 6. out_proj: out[4096,1024] = y @ W_out^T (K=2048)
    mma_tn<0><<<dim3(16, 32, 1), blk, MMA_SMEM_BYTES>>>(yh, whout, out,
        NROWS, DMODEL, DINNER, DINNER, DINNER, DMODEL,
        nullptr, DINNER);
}